// round 13
// baseline (speedup 1.0000x reference)
#include <cuda_runtime.h>
#include <cuda_fp16.h>
#include <cstdint>
#include <cstddef>

#define NU 100000
#define NVV 100000
#define DD 128
#define RR 5
#define OO 64
#define EE 640000

#define GEMM_TILES 782                 /* ceil(100000/128) */

// spmm block shapes: overlap phase uses 768-thr blocks (96 edges) so greedy
// fill = 2 CTAs/SM = 1536 thr, reserving 512 thr for a co-resident gemm CTA.
// solo phase uses 256-thr blocks (32 edges) for full occupancy.
#define SPMM_BPR_OVL ((EE + 95) / 96)   /* 6667 */
#define SPMM_BPR_SOLO (EE / 32)         /* 20000 */

// ---------------------------------------------------------------------------
// Scratch (static device globals) — tmp in fp16
// ---------------------------------------------------------------------------
__device__ __half g_tmpU[(size_t)RR * NU * OO];   // [r][n][64]
__device__ __half g_tmpV[(size_t)RR * NVV * OO];
// Pre-swizzled fp16 B images: 16KB per relation.
// Layout: row n (0..63) * 256B, 16B chunk c at (c ^ (n&7)).
__device__ unsigned char g_BimgU[RR * 16384];
__device__ unsigned char g_BimgV[RR * 16384];

// ---------------------------------------------------------------------------
// helpers
// ---------------------------------------------------------------------------
__device__ __forceinline__ uint32_t smem_u32(const void* p) {
    uint32_t a;
    asm("{ .reg .u64 t; cvta.to.shared.u64 t, %1; cvt.u32.u64 %0, t; }"
        : "=r"(a) : "l"(p));
    return a;
}
__device__ __forceinline__ void ldsm4(uint32_t addr, uint32_t& r0, uint32_t& r1,
                                      uint32_t& r2, uint32_t& r3) {
    asm volatile("ldmatrix.sync.aligned.m8n8.x4.shared.b16 {%0,%1,%2,%3}, [%4];"
                 : "=r"(r0), "=r"(r1), "=r"(r2), "=r"(r3) : "r"(addr));
}
__device__ __forceinline__ void mma_f16(float* d, const uint32_t* a,
                                        uint32_t b0, uint32_t b1) {
    asm volatile(
        "mma.sync.aligned.m16n8k16.row.col.f32.f16.f16.f32 "
        "{%0,%1,%2,%3}, {%4,%5,%6,%7}, {%8,%9}, {%0,%1,%2,%3};"
        : "+f"(d[0]), "+f"(d[1]), "+f"(d[2]), "+f"(d[3])
        : "r"(a[0]), "r"(a[1]), "r"(a[2]), "r"(a[3]), "r"(b0), "r"(b1));
}

// ---------------------------------------------------------------------------
// cumsum weights + pack swizzled fp16 B images (k = d, n = o)
// ---------------------------------------------------------------------------
__global__ void cumsum_pack_kernel(const float* __restrict__ wu,
                                   const float* __restrict__ wv,
                                   unsigned char* __restrict__ imgU,
                                   unsigned char* __restrict__ imgV)
{
    int i = blockIdx.x * blockDim.x + threadIdx.x;
    if (i >= DD * OO) return;
    const float* w    = blockIdx.y ? wv : wu;
    unsigned char* im = blockIdx.y ? imgV : imgU;
    int k = i >> 6, n = i & 63;
    uint32_t off = (uint32_t)n * 256 + ((((k >> 3) ^ (n & 7))) << 4) + (k & 7) * 2;
    float s = 0.f;
#pragma unroll
    for (int r = 0; r < RR; r++) {
        s += w[r * DD * OO + i];
        *(__half*)(im + r * 16384 + off) = __float2half_rn(s);
    }
}

// ---------------------------------------------------------------------------
// GEMM: one CTA = 128-row tile, all 5 relations. Single-pass fp16 MMA.
// SMEM: A 32KB | B 5*16KB = 112KB. 256 thr, warp tile 32x32.
// ---------------------------------------------------------------------------
#define OFF_A 0
#define OFF_B 32768
#define GT_SMEM (32768 + RR * 16384)   /* 114688 */

__global__ void __launch_bounds__(256, 2)
gemm_tc_kernel(const float* __restrict__ A,
               const unsigned char* __restrict__ Bimg,
               __half* __restrict__ C, int M)
{
    extern __shared__ unsigned char smem[];
    const int tid  = threadIdx.x;
    const int wid  = tid >> 5;
    const int lane = tid & 31;
    const int m0   = blockIdx.x * 128;

    // ---- A tile: fp32 load -> fp16 swizzled smem (once) ----
    for (int idx = tid; idx < 2048; idx += 256) {
        int m = idx >> 4, c = idx & 15, k0 = c << 3;
        float4 v0 = make_float4(0, 0, 0, 0), v1 = make_float4(0, 0, 0, 0);
        if (m0 + m < M) {
            const float* ap = A + (size_t)(m0 + m) * DD + k0;
            v0 = *(const float4*)ap;
            v1 = *(const float4*)(ap + 4);
        }
        __half2 h0 = __floats2half2_rn(v0.x, v0.y);
        __half2 h1 = __floats2half2_rn(v0.z, v0.w);
        __half2 h2 = __floats2half2_rn(v1.x, v1.y);
        __half2 h3 = __floats2half2_rn(v1.z, v1.w);
        uint32_t off = (uint32_t)m * 256 + ((c ^ (m & 7)) << 4);
        *(uint4*)(smem + OFF_A + off) =
            make_uint4(*(uint32_t*)&h0, *(uint32_t*)&h1,
                       *(uint32_t*)&h2, *(uint32_t*)&h3);
    }
    // ---- B: bulk copy all 5 pre-swizzled images (80KB) ----
    {
        const uint4* src = (const uint4*)Bimg;
        uint4* dst = (uint4*)(smem + OFF_B);
        for (int i = tid; i < (RR * 16384) / 16; i += 256) dst[i] = src[i];
    }
    __syncthreads();

    const int mbase = (wid >> 1) * 32;
    const int nbase = (wid & 1) * 32;
    const uint32_t sb = smem_u32(smem);
    const uint32_t abase = sb + OFF_A;
    const int a_m  = mbase + (lane & 15);
    const int a_cb = lane >> 4;
    const int b_n  = nbase + (lane & 7) + ((lane >> 4) & 1) * 8;
    const int b_cb = (lane >> 3) & 1;
    const int grp4 = lane >> 2, tg = lane & 3;

    for (int g = 0; g < RR; g++) {
        const uint32_t bbase = sb + OFF_B + g * 16384;

        float acc[2][4][4];
#pragma unroll
        for (int i = 0; i < 2; i++)
#pragma unroll
            for (int j = 0; j < 4; j++)
#pragma unroll
                for (int q = 0; q < 4; q++) acc[i][j][q] = 0.f;

        uint32_t afr[2][2][4], bfr[2][2][4];   // [buf][mt|pr][frag]
        auto load_frags = [&](int ks, int buf) {
            const int c = ks * 2;
#pragma unroll
            for (int mt = 0; mt < 2; mt++) {
                int m = a_m + mt * 16, cc = c + a_cb;
                uint32_t ad = abase + (uint32_t)m * 256 + ((cc ^ (m & 7)) << 4);
                ldsm4(ad, afr[buf][mt][0], afr[buf][mt][1],
                          afr[buf][mt][2], afr[buf][mt][3]);
            }
#pragma unroll
            for (int pr = 0; pr < 2; pr++) {
                int n = b_n + pr * 16, cc = c + b_cb;
                uint32_t bd = bbase + (uint32_t)n * 256 + ((cc ^ (n & 7)) << 4);
                ldsm4(bd, bfr[buf][pr][0], bfr[buf][pr][1],
                          bfr[buf][pr][2], bfr[buf][pr][3]);
            }
        };
        load_frags(0, 0);
#pragma unroll
        for (int ks = 0; ks < 8; ks++) {
            const int cur = ks & 1;
            if (ks < 7) load_frags(ks + 1, cur ^ 1);
#pragma unroll
            for (int mt = 0; mt < 2; mt++)
#pragma unroll
                for (int nt = 0; nt < 4; nt++)
                    mma_f16(acc[mt][nt], afr[cur][mt],
                            bfr[cur][nt >> 1][(nt & 1) * 2],
                            bfr[cur][nt >> 1][(nt & 1) * 2 + 1]);
        }

        // ---- epilogue: fp16 half2 stores ----
#pragma unroll
        for (int mt = 0; mt < 2; mt++)
#pragma unroll
            for (int nt = 0; nt < 4; nt++) {
                int row0 = m0 + mbase + mt * 16 + grp4;
                int col  = nbase + nt * 8 + tg * 2;
                if (row0 < M)
                    *(__half2*)&C[((size_t)g * M + row0) * OO + col] =
                        __floats2half2_rn(acc[mt][nt][0], acc[mt][nt][1]);
                int row1 = row0 + 8;
                if (row1 < M)
                    *(__half2*)&C[((size_t)g * M + row1) * OO + col] =
                        __floats2half2_rn(acc[mt][nt][2], acc[mt][nt][3]);
            }
        // no sync needed: smem is read-only across relations
    }
}

// ---------------------------------------------------------------------------
// SpMM: 16 lanes/edge, 2 edges/group, fp16 gathers, fp32 red.v4 scatter.
// Block-size agnostic: edges per block = blockDim/8. Launched at 768 thr
// during the overlap phase (thread-count reserves a gemm slot per SM) and
// 256 thr during the solo phase.
// ---------------------------------------------------------------------------
__global__ void __launch_bounds__(768)
spmm_kernel(const int* __restrict__ rows, const int* __restrict__ cols,
            const float* __restrict__ vals, const __half* __restrict__ tmp,
            float* __restrict__ z)
{
    const int rel = blockIdx.y;
    const int grp = threadIdx.x >> 4;
    const int l16 = threadIdx.x & 15;
    const int e   = blockIdx.x * (blockDim.x >> 3) + grp * 2;
    if (e >= EE) return;
    const size_t eo = (size_t)rel * EE + e;

    int2 rw = make_int2(0, 0), cl = make_int2(0, 0);
    float2 vv = make_float2(0.f, 0.f);
    if (l16 == 0) {
        rw = *(const int2*)(rows + eo);
        cl = *(const int2*)(cols + eo);
        vv = *(const float2*)(vals + eo);
    }
    int   row0 = __shfl_sync(0xffffffffu, rw.x, 0, 16);
    int   row1 = __shfl_sync(0xffffffffu, rw.y, 0, 16);
    int   col0 = __shfl_sync(0xffffffffu, cl.x, 0, 16);
    int   col1 = __shfl_sync(0xffffffffu, cl.y, 0, 16);
    float v0   = __shfl_sync(0xffffffffu, vv.x, 0, 16);
    float v1   = __shfl_sync(0xffffffffu, vv.y, 0, 16);

    const uint2* tb = (const uint2*)(tmp + (size_t)rel * 100000 * OO);
    uint2 t0 = __ldg(tb + (size_t)col0 * 16 + l16);
    uint2 t1 = __ldg(tb + (size_t)col1 * 16 + l16);

    float2 a0 = __half22float2(*(__half2*)&t0.x);
    float2 a1 = __half22float2(*(__half2*)&t0.y);
    float2 b0 = __half22float2(*(__half2*)&t1.x);
    float2 b1 = __half22float2(*(__half2*)&t1.y);

    float* d0 = z + (size_t)row0 * OO + (l16 << 2);
    float* d1 = z + (size_t)row1 * OO + (l16 << 2);
    asm volatile("red.global.add.v4.f32 [%0], {%1, %2, %3, %4};"
                 :: "l"(d0), "f"(a0.x * v0), "f"(a0.y * v0),
                    "f"(a1.x * v0), "f"(a1.y * v0)
                 : "memory");
    asm volatile("red.global.add.v4.f32 [%0], {%1, %2, %3, %4};"
                 :: "l"(d1), "f"(b0.x * v1), "f"(b0.y * v1),
                    "f"(b1.x * v1), "f"(b1.y * v1)
                 : "memory");
}

// ---------------------------------------------------------------------------
// zero / relu
// ---------------------------------------------------------------------------
__global__ void zero_kernel(float4* __restrict__ p, int n4)
{
    int i = blockIdx.x * blockDim.x + threadIdx.x;
    if (i < n4) p[i] = make_float4(0.f, 0.f, 0.f, 0.f);
}
__global__ void relu_kernel(float4* __restrict__ p, int n4)
{
    int i = blockIdx.x * blockDim.x + threadIdx.x;
    if (i < n4) {
        float4 v = p[i];
        v.x = fmaxf(v.x, 0.f); v.y = fmaxf(v.y, 0.f);
        v.z = fmaxf(v.z, 0.f); v.w = fmaxf(v.w, 0.f);
        p[i] = v;
    }
}

// ---------------------------------------------------------------------------
// kernel_launch — forked-stream schedule with thread-count slot reservation:
//   cumsum -> [gemmV (s0) || zero (s2)]
//          -> [spmmV@768thr (s0) || gemmU (s2 hi-prio, gated on gemmV)]
//          -> [spmmU@256thr (s0) || relu z_u (s2)]
//          -> relu z_v (s0); join.
// ---------------------------------------------------------------------------
extern "C" void kernel_launch(void* const* d_in, const int* in_sizes, int n_in,
                              void* d_out, int out_size)
{
    const float* x_u  = (const float*)d_in[0];
    const float* x_v  = (const float*)d_in[1];
    const int*   srow = (const int*)d_in[2];
    const int*   scol = (const int*)d_in[3];
    const float* sval = (const float*)d_in[4];
    const float* wu   = (const float*)d_in[5];
    const float* wv   = (const float*)d_in[6];

    float* out = (float*)d_out;
    float* z_u = out;
    float* z_v = out + (size_t)NU * OO;

    __half *tmpU, *tmpV;
    unsigned char *BiU, *BiV;
    cudaGetSymbolAddress((void**)&tmpU, g_tmpU);
    cudaGetSymbolAddress((void**)&tmpV, g_tmpV);
    cudaGetSymbolAddress((void**)&BiU, g_BimgU);
    cudaGetSymbolAddress((void**)&BiV, g_BimgV);

    static cudaStream_t s2 = nullptr;
    static cudaEvent_t evC, evZero, evGemmV, evGemmU, evSpV, evJoin;
    if (!s2) {
        int loPrio, hiPrio;
        cudaDeviceGetStreamPriorityRange(&loPrio, &hiPrio);
        cudaStreamCreateWithPriority(&s2, cudaStreamNonBlocking, hiPrio);
        cudaEventCreateWithFlags(&evC,     cudaEventDisableTiming);
        cudaEventCreateWithFlags(&evZero,  cudaEventDisableTiming);
        cudaEventCreateWithFlags(&evGemmV, cudaEventDisableTiming);
        cudaEventCreateWithFlags(&evGemmU, cudaEventDisableTiming);
        cudaEventCreateWithFlags(&evSpV,   cudaEventDisableTiming);
        cudaEventCreateWithFlags(&evJoin,  cudaEventDisableTiming);
        cudaFuncSetAttribute(gemm_tc_kernel,
                             cudaFuncAttributeMaxDynamicSharedMemorySize,
                             GT_SMEM);
    }

    const int n4 = (NU * OO + NVV * OO) / 4;        // 3.2M float4

    // stage 0: cumsum (s0); fork zero to s2
    cumsum_pack_kernel<<<dim3((DD * OO + 255) / 256, 2), 256>>>(wu, wv, BiU, BiV);
    cudaEventRecord(evC, 0);
    cudaStreamWaitEvent(s2, evC, 0);

    // stage 1: gemmV (s0)  ||  zero out (s2)
    zero_kernel<<<(n4 + 255) / 256, 256, 0, s2>>>((float4*)out, n4);
    cudaEventRecord(evZero, s2);
    gemm_tc_kernel<<<GEMM_TILES, 256, GT_SMEM>>>(x_v, BiV, tmpV, NVV);
    cudaEventRecord(evGemmV, 0);

    // stage 2: spmmV@768 (s0, needs zero)  ||  gemmU (s2, gated on gemmV)
    cudaStreamWaitEvent(0, evZero, 0);
    spmm_kernel<<<dim3(SPMM_BPR_OVL, RR), 768>>>(srow, scol, sval, tmpV, z_u);
    cudaEventRecord(evSpV, 0);
    cudaStreamWaitEvent(s2, evGemmV, 0);
    gemm_tc_kernel<<<GEMM_TILES, 256, GT_SMEM, s2>>>(x_u, BiU, tmpU, NU);
    cudaEventRecord(evGemmU, s2);

    // stage 3: spmmU@256 (s0, needs tmpU)  ||  relu z_u (s2, needs spmmV)
    cudaStreamWaitEvent(0, evGemmU, 0);
    spmm_kernel<<<dim3(SPMM_BPR_SOLO, RR), 256>>>(scol, srow, sval, tmpU, z_v);
    cudaStreamWaitEvent(s2, evSpV, 0);
    relu_kernel<<<(n4 / 2 + 255) / 256, 256, 0, s2>>>((float4*)z_u, n4 / 2);
    cudaEventRecord(evJoin, s2);

    // stage 4: relu z_v (s0); join
    relu_kernel<<<(n4 / 2 + 255) / 256, 256>>>((float4*)z_v, n4 / 2);
    cudaStreamWaitEvent(0, evJoin, 0);
}

// round 16
// speedup vs baseline: 1.1678x; 1.1678x over previous
#include <cuda_runtime.h>
#include <cuda_fp16.h>
#include <cstdint>
#include <cstddef>

#define NU 100000
#define NVV 100000
#define DD 128
#define RR 5
#define OO 64
#define EE 640000

#define GEMM_TILES 782                 /* ceil(100000/128) */
#define SPMM_BPR   20000               /* 640000 / 32 edges per block */

// ---------------------------------------------------------------------------
// Scratch (static device globals) — tmp in fp16
// ---------------------------------------------------------------------------
__device__ __half g_tmpU[(size_t)RR * NU * OO];   // [r][n][64]
__device__ __half g_tmpV[(size_t)RR * NVV * OO];
// Pre-swizzled fp16 B images: 16KB per relation.
// Layout: row n (0..63) * 256B, 16B chunk c at (c ^ (n&7)).
__device__ unsigned char g_BimgU[RR * 16384];
__device__ unsigned char g_BimgV[RR * 16384];

// ---------------------------------------------------------------------------
// helpers
// ---------------------------------------------------------------------------
__device__ __forceinline__ uint32_t smem_u32(const void* p) {
    uint32_t a;
    asm("{ .reg .u64 t; cvta.to.shared.u64 t, %1; cvt.u32.u64 %0, t; }"
        : "=r"(a) : "l"(p));
    return a;
}
__device__ __forceinline__ void ldsm4(uint32_t addr, uint32_t& r0, uint32_t& r1,
                                      uint32_t& r2, uint32_t& r3) {
    asm volatile("ldmatrix.sync.aligned.m8n8.x4.shared.b16 {%0,%1,%2,%3}, [%4];"
                 : "=r"(r0), "=r"(r1), "=r"(r2), "=r"(r3) : "r"(addr));
}
__device__ __forceinline__ void mma_f16(float* d, const uint32_t* a,
                                        uint32_t b0, uint32_t b1) {
    asm volatile(
        "mma.sync.aligned.m16n8k16.row.col.f32.f16.f16.f32 "
        "{%0,%1,%2,%3}, {%4,%5,%6,%7}, {%8,%9}, {%0,%1,%2,%3};"
        : "+f"(d[0]), "+f"(d[1]), "+f"(d[2]), "+f"(d[3])
        : "r"(a[0]), "r"(a[1]), "r"(a[2]), "r"(a[3]), "r"(b0), "r"(b1));
}

// ---------------------------------------------------------------------------
// cumsum weights + pack swizzled fp16 B images (k = d, n = o)
// ---------------------------------------------------------------------------
__global__ void cumsum_pack_kernel(const float* __restrict__ wu,
                                   const float* __restrict__ wv,
                                   unsigned char* __restrict__ imgU,
                                   unsigned char* __restrict__ imgV)
{
    int i = blockIdx.x * blockDim.x + threadIdx.x;
    if (i >= DD * OO) return;
    const float* w    = blockIdx.y ? wv : wu;
    unsigned char* im = blockIdx.y ? imgV : imgU;
    int k = i >> 6, n = i & 63;
    uint32_t off = (uint32_t)n * 256 + ((((k >> 3) ^ (n & 7))) << 4) + (k & 7) * 2;
    float s = 0.f;
#pragma unroll
    for (int r = 0; r < RR; r++) {
        s += w[r * DD * OO + i];
        *(__half*)(im + r * 16384 + off) = __float2half_rn(s);
    }
}

// ---------------------------------------------------------------------------
// GEMM: one CTA = 128-row tile, loops over all 5 relations.
// Single-pass fp16 MMA, B staged per relation (16KB), single-buffered frags.
// SMEM: A 32KB | B 16KB = 48KB -> 3 CTAs/SM (24 warps). 256 thr, warp 32x32.
// ---------------------------------------------------------------------------
#define OFF_A 0
#define OFF_B 32768
#define GT_SMEM 49152

__global__ void __launch_bounds__(256, 3)
gemm_tc_kernel(const float* __restrict__ A,
               const unsigned char* __restrict__ Bimg,
               __half* __restrict__ C, int M)
{
    extern __shared__ unsigned char smem[];
    const int tid  = threadIdx.x;
    const int wid  = tid >> 5;
    const int lane = tid & 31;
    const int m0   = blockIdx.x * 128;

    // ---- A tile: fp32 load -> fp16 swizzled smem (once) ----
    for (int idx = tid; idx < 2048; idx += 256) {
        int m = idx >> 4, c = idx & 15, k0 = c << 3;
        float4 v0 = make_float4(0, 0, 0, 0), v1 = make_float4(0, 0, 0, 0);
        if (m0 + m < M) {
            const float* ap = A + (size_t)(m0 + m) * DD + k0;
            v0 = *(const float4*)ap;
            v1 = *(const float4*)(ap + 4);
        }
        __half2 h0 = __floats2half2_rn(v0.x, v0.y);
        __half2 h1 = __floats2half2_rn(v0.z, v0.w);
        __half2 h2 = __floats2half2_rn(v1.x, v1.y);
        __half2 h3 = __floats2half2_rn(v1.z, v1.w);
        uint32_t off = (uint32_t)m * 256 + ((c ^ (m & 7)) << 4);
        *(uint4*)(smem + OFF_A + off) =
            make_uint4(*(uint32_t*)&h0, *(uint32_t*)&h1,
                       *(uint32_t*)&h2, *(uint32_t*)&h3);
    }

    const int mbase = (wid >> 1) * 32;
    const int nbase = (wid & 1) * 32;
    const uint32_t sb = smem_u32(smem);
    const uint32_t abase = sb + OFF_A;
    const uint32_t bbase = sb + OFF_B;
    const int a_m  = mbase + (lane & 15);
    const int a_cb = lane >> 4;
    const int b_n  = nbase + (lane & 7) + ((lane >> 4) & 1) * 8;
    const int b_cb = (lane >> 3) & 1;
    const int grp4 = lane >> 2, tg = lane & 3;

    for (int g = 0; g < RR; g++) {
        // ---- stage B image for relation g (16KB) ----
        if (g > 0) __syncthreads();     // prior mainloop LDSMs done
        {
            const uint4* src = (const uint4*)(Bimg + (size_t)g * 16384);
            uint4* dst = (uint4*)(smem + OFF_B);
#pragma unroll
            for (int i = 0; i < 4; i++) dst[tid + i * 256] = src[tid + i * 256];
        }
        __syncthreads();

        float acc[2][4][4];
#pragma unroll
        for (int i = 0; i < 2; i++)
#pragma unroll
            for (int j = 0; j < 4; j++)
#pragma unroll
                for (int q = 0; q < 4; q++) acc[i][j][q] = 0.f;

#pragma unroll
        for (int ks = 0; ks < 8; ks++) {
            const int c = ks * 2;
            uint32_t afr[2][4], bfr[2][4];
#pragma unroll
            for (int mt = 0; mt < 2; mt++) {
                int m = a_m + mt * 16, cc = c + a_cb;
                uint32_t ad = abase + (uint32_t)m * 256 + ((cc ^ (m & 7)) << 4);
                ldsm4(ad, afr[mt][0], afr[mt][1], afr[mt][2], afr[mt][3]);
            }
#pragma unroll
            for (int pr = 0; pr < 2; pr++) {
                int n = b_n + pr * 16, cc = c + b_cb;
                uint32_t bd = bbase + (uint32_t)n * 256 + ((cc ^ (n & 7)) << 4);
                ldsm4(bd, bfr[pr][0], bfr[pr][1], bfr[pr][2], bfr[pr][3]);
            }
#pragma unroll
            for (int mt = 0; mt < 2; mt++)
#pragma unroll
                for (int nt = 0; nt < 4; nt++)
                    mma_f16(acc[mt][nt], afr[mt],
                            bfr[nt >> 1][(nt & 1) * 2],
                            bfr[nt >> 1][(nt & 1) * 2 + 1]);
        }

        // ---- epilogue: fp16 half2 stores (regs+global only, no smem) ----
#pragma unroll
        for (int mt = 0; mt < 2; mt++)
#pragma unroll
            for (int nt = 0; nt < 4; nt++) {
                int row0 = m0 + mbase + mt * 16 + grp4;
                int col  = nbase + nt * 8 + tg * 2;
                if (row0 < M)
                    *(__half2*)&C[((size_t)g * M + row0) * OO + col] =
                        __floats2half2_rn(acc[mt][nt][0], acc[mt][nt][1]);
                int row1 = row0 + 8;
                if (row1 < M)
                    *(__half2*)&C[((size_t)g * M + row1) * OO + col] =
                        __floats2half2_rn(acc[mt][nt][2], acc[mt][nt][3]);
            }
    }
}

// ---------------------------------------------------------------------------
// SpMM: 16 lanes/edge, 2 edges/group, fp16 gathers, fp32 red.v4 scatter.
// block = 256 threads = 32 edges. grid = (20000, RR).
// ---------------------------------------------------------------------------
__global__ void __launch_bounds__(256)
spmm_kernel(const int* __restrict__ rows, const int* __restrict__ cols,
            const float* __restrict__ vals, const __half* __restrict__ tmp,
            float* __restrict__ z)
{
    const int rel = blockIdx.y;
    const int grp = threadIdx.x >> 4;
    const int l16 = threadIdx.x & 15;
    const int e   = blockIdx.x * 32 + grp * 2;
    const size_t eo = (size_t)rel * EE + e;

    int2 rw = make_int2(0, 0), cl = make_int2(0, 0);
    float2 vv = make_float2(0.f, 0.f);
    if (l16 == 0) {
        rw = *(const int2*)(rows + eo);
        cl = *(const int2*)(cols + eo);
        vv = *(const float2*)(vals + eo);
    }
    int   row0 = __shfl_sync(0xffffffffu, rw.x, 0, 16);
    int   row1 = __shfl_sync(0xffffffffu, rw.y, 0, 16);
    int   col0 = __shfl_sync(0xffffffffu, cl.x, 0, 16);
    int   col1 = __shfl_sync(0xffffffffu, cl.y, 0, 16);
    float v0   = __shfl_sync(0xffffffffu, vv.x, 0, 16);
    float v1   = __shfl_sync(0xffffffffu, vv.y, 0, 16);

    const uint2* tb = (const uint2*)(tmp + (size_t)rel * 100000 * OO);
    uint2 t0 = __ldg(tb + (size_t)col0 * 16 + l16);
    uint2 t1 = __ldg(tb + (size_t)col1 * 16 + l16);

    float2 a0 = __half22float2(*(__half2*)&t0.x);
    float2 a1 = __half22float2(*(__half2*)&t0.y);
    float2 b0 = __half22float2(*(__half2*)&t1.x);
    float2 b1 = __half22float2(*(__half2*)&t1.y);

    float* d0 = z + (size_t)row0 * OO + (l16 << 2);
    float* d1 = z + (size_t)row1 * OO + (l16 << 2);
    asm volatile("red.global.add.v4.f32 [%0], {%1, %2, %3, %4};"
                 :: "l"(d0), "f"(a0.x * v0), "f"(a0.y * v0),
                    "f"(a1.x * v0), "f"(a1.y * v0)
                 : "memory");
    asm volatile("red.global.add.v4.f32 [%0], {%1, %2, %3, %4};"
                 :: "l"(d1), "f"(b0.x * v1), "f"(b0.y * v1),
                    "f"(b1.x * v1), "f"(b1.y * v1)
                 : "memory");
}

// ---------------------------------------------------------------------------
// zero / relu
// ---------------------------------------------------------------------------
__global__ void zero_kernel(float4* __restrict__ p, int n4)
{
    int i = blockIdx.x * blockDim.x + threadIdx.x;
    if (i < n4) p[i] = make_float4(0.f, 0.f, 0.f, 0.f);
}
__global__ void relu_kernel(float4* __restrict__ p, int n4)
{
    int i = blockIdx.x * blockDim.x + threadIdx.x;
    if (i < n4) {
        float4 v = p[i];
        v.x = fmaxf(v.x, 0.f); v.y = fmaxf(v.y, 0.f);
        v.z = fmaxf(v.z, 0.f); v.w = fmaxf(v.w, 0.f);
        p[i] = v;
    }
}

// ---------------------------------------------------------------------------
// kernel_launch — R11 schedule (best at 428us), verbatim:
//   cumsum -> [gemmV || zero(out)] -> [spmmV || gemmU] -> [spmmU || relu_u]
//   -> relu_v ; join.
// ---------------------------------------------------------------------------
extern "C" void kernel_launch(void* const* d_in, const int* in_sizes, int n_in,
                              void* d_out, int out_size)
{
    const float* x_u  = (const float*)d_in[0];
    const float* x_v  = (const float*)d_in[1];
    const int*   srow = (const int*)d_in[2];
    const int*   scol = (const int*)d_in[3];
    const float* sval = (const float*)d_in[4];
    const float* wu   = (const float*)d_in[5];
    const float* wv   = (const float*)d_in[6];

    float* out = (float*)d_out;
    float* z_u = out;
    float* z_v = out + (size_t)NU * OO;

    __half *tmpU, *tmpV;
    unsigned char *BiU, *BiV;
    cudaGetSymbolAddress((void**)&tmpU, g_tmpU);
    cudaGetSymbolAddress((void**)&tmpV, g_tmpV);
    cudaGetSymbolAddress((void**)&BiU, g_BimgU);
    cudaGetSymbolAddress((void**)&BiV, g_BimgV);

    static cudaStream_t s2 = nullptr;
    static cudaEvent_t evFork, evZero, evGemmU, evZu, evJoin;
    if (!s2) {
        cudaStreamCreateWithFlags(&s2, cudaStreamNonBlocking);
        cudaEventCreateWithFlags(&evFork,  cudaEventDisableTiming);
        cudaEventCreateWithFlags(&evZero,  cudaEventDisableTiming);
        cudaEventCreateWithFlags(&evGemmU, cudaEventDisableTiming);
        cudaEventCreateWithFlags(&evZu,    cudaEventDisableTiming);
        cudaEventCreateWithFlags(&evJoin,  cudaEventDisableTiming);
        cudaFuncSetAttribute(gemm_tc_kernel,
                             cudaFuncAttributeMaxDynamicSharedMemorySize,
                             GT_SMEM);
    }

    const int n4 = (NU * OO + NVV * OO) / 4;        // 3.2M float4

    // stage 0: cumsum (stream 0), then fork
    cumsum_pack_kernel<<<dim3((DD * OO + 255) / 256, 2), 256>>>(wu, wv, BiU, BiV);
    cudaEventRecord(evFork, 0);
    cudaStreamWaitEvent(s2, evFork, 0);

    // stage 1: gemmV (stream 0)  ||  zero whole out (s2)
    zero_kernel<<<(n4 + 255) / 256, 256, 0, s2>>>((float4*)out, n4);
    gemm_tc_kernel<<<GEMM_TILES, 256, GT_SMEM>>>(x_v, BiV, tmpV, NVV);
    cudaEventRecord(evZero, s2);
    cudaStreamWaitEvent(0, evZero, 0);       // spmmV needs z_u zeroed
    cudaEventRecord(evFork, 0);              // gemmV + zero both done here
    cudaStreamWaitEvent(s2, evFork, 0);

    // stage 2: spmmV -> z_u (stream 0)  ||  gemmU -> tmpU (s2)
    gemm_tc_kernel<<<GEMM_TILES, 256, GT_SMEM, s2>>>(x_u, BiU, tmpU, NU);
    spmm_kernel<<<dim3(SPMM_BPR, RR), 256>>>(srow, scol, sval, tmpV, z_u);
    cudaEventRecord(evGemmU, s2);
    cudaStreamWaitEvent(0, evGemmU, 0);      // spmmU needs tmpU
    cudaEventRecord(evZu, 0);                // z_u final after spmmV
    cudaStreamWaitEvent(s2, evZu, 0);

    // stage 3: spmmU -> z_v (stream 0)  ||  relu z_u (s2)
    relu_kernel<<<(n4 / 2 + 255) / 256, 256, 0, s2>>>((float4*)z_u, n4 / 2);
    spmm_kernel<<<dim3(SPMM_BPR, RR), 256>>>(scol, srow, sval, tmpU, z_v);

    // stage 4: relu z_v (stream 0); join s2
    relu_kernel<<<(n4 / 2 + 255) / 256, 256>>>((float4*)z_v, n4 / 2);
    cudaEventRecord(evJoin, s2);
    cudaStreamWaitEvent(0, evJoin, 0);
}

// round 17
// speedup vs baseline: 1.7742x; 1.5193x over previous
#include <cuda_runtime.h>
#include <cuda_fp16.h>
#include <cstdint>
#include <cstddef>

#define NU 100000
#define NVV 100000
#define DD 128
#define RR 5
#define OO 64
#define EE 640000

#define GEMM_TILES 782                 /* ceil(100000/128) */
#define SPMM_BPR   10000               /* 640000 / 64 edges per block */

// ---------------------------------------------------------------------------
// Scratch (static device globals)
// ---------------------------------------------------------------------------
__device__ __half g_tmpU[(size_t)RR * NU * OO];   // [r][n][64] fp16
__device__ __half g_tmpV[(size_t)RR * NVV * OO];
__device__ __half g_zh[(size_t)2 * 100000 * OO];  // fp16 accumulators (z_u|z_v)
// Pre-swizzled fp16 B images: 16KB per relation.
__device__ unsigned char g_BimgU[RR * 16384];
__device__ unsigned char g_BimgV[RR * 16384];

// ---------------------------------------------------------------------------
// helpers
// ---------------------------------------------------------------------------
__device__ __forceinline__ uint32_t smem_u32(const void* p) {
    uint32_t a;
    asm("{ .reg .u64 t; cvta.to.shared.u64 t, %1; cvt.u32.u64 %0, t; }"
        : "=r"(a) : "l"(p));
    return a;
}
__device__ __forceinline__ void ldsm4(uint32_t addr, uint32_t& r0, uint32_t& r1,
                                      uint32_t& r2, uint32_t& r3) {
    asm volatile("ldmatrix.sync.aligned.m8n8.x4.shared.b16 {%0,%1,%2,%3}, [%4];"
                 : "=r"(r0), "=r"(r1), "=r"(r2), "=r"(r3) : "r"(addr));
}
__device__ __forceinline__ void mma_f16(float* d, const uint32_t* a,
                                        uint32_t b0, uint32_t b1) {
    asm volatile(
        "mma.sync.aligned.m16n8k16.row.col.f32.f16.f16.f32 "
        "{%0,%1,%2,%3}, {%4,%5,%6,%7}, {%8,%9}, {%0,%1,%2,%3};"
        : "+f"(d[0]), "+f"(d[1]), "+f"(d[2]), "+f"(d[3])
        : "r"(a[0]), "r"(a[1]), "r"(a[2]), "r"(a[3]), "r"(b0), "r"(b1));
}

// ---------------------------------------------------------------------------
// cumsum weights + pack swizzled fp16 B images (k = d, n = o)
// ---------------------------------------------------------------------------
__global__ void cumsum_pack_kernel(const float* __restrict__ wu,
                                   const float* __restrict__ wv,
                                   unsigned char* __restrict__ imgU,
                                   unsigned char* __restrict__ imgV)
{
    int i = blockIdx.x * blockDim.x + threadIdx.x;
    if (i >= DD * OO) return;
    const float* w    = blockIdx.y ? wv : wu;
    unsigned char* im = blockIdx.y ? imgV : imgU;
    int k = i >> 6, n = i & 63;
    uint32_t off = (uint32_t)n * 256 + ((((k >> 3) ^ (n & 7))) << 4) + (k & 7) * 2;
    float s = 0.f;
#pragma unroll
    for (int r = 0; r < RR; r++) {
        s += w[r * DD * OO + i];
        *(__half*)(im + r * 16384 + off) = __float2half_rn(s);
    }
}

// ---------------------------------------------------------------------------
// GEMM: one CTA = 128-row tile, loops over all 5 relations.
// Single-pass fp16 MMA, B staged per relation (16KB), single-buffered frags.
// SMEM: A 32KB | B 16KB = 48KB -> 3 CTAs/SM (24 warps). 256 thr, warp 32x32.
// ---------------------------------------------------------------------------
#define OFF_A 0
#define OFF_B 32768
#define GT_SMEM 49152

__global__ void __launch_bounds__(256, 3)
gemm_tc_kernel(const float* __restrict__ A,
               const unsigned char* __restrict__ Bimg,
               __half* __restrict__ C, int M)
{
    extern __shared__ unsigned char smem[];
    const int tid  = threadIdx.x;
    const int wid  = tid >> 5;
    const int lane = tid & 31;
    const int m0   = blockIdx.x * 128;

    // ---- A tile: fp32 load -> fp16 swizzled smem (once) ----
    for (int idx = tid; idx < 2048; idx += 256) {
        int m = idx >> 4, c = idx & 15, k0 = c << 3;
        float4 v0 = make_float4(0, 0, 0, 0), v1 = make_float4(0, 0, 0, 0);
        if (m0 + m < M) {
            const float* ap = A + (size_t)(m0 + m) * DD + k0;
            v0 = *(const float4*)ap;
            v1 = *(const float4*)(ap + 4);
        }
        __half2 h0 = __floats2half2_rn(v0.x, v0.y);
        __half2 h1 = __floats2half2_rn(v0.z, v0.w);
        __half2 h2 = __floats2half2_rn(v1.x, v1.y);
        __half2 h3 = __floats2half2_rn(v1.z, v1.w);
        uint32_t off = (uint32_t)m * 256 + ((c ^ (m & 7)) << 4);
        *(uint4*)(smem + OFF_A + off) =
            make_uint4(*(uint32_t*)&h0, *(uint32_t*)&h1,
                       *(uint32_t*)&h2, *(uint32_t*)&h3);
    }

    const int mbase = (wid >> 1) * 32;
    const int nbase = (wid & 1) * 32;
    const uint32_t sb = smem_u32(smem);
    const uint32_t abase = sb + OFF_A;
    const uint32_t bbase = sb + OFF_B;
    const int a_m  = mbase + (lane & 15);
    const int a_cb = lane >> 4;
    const int b_n  = nbase + (lane & 7) + ((lane >> 4) & 1) * 8;
    const int b_cb = (lane >> 3) & 1;
    const int grp4 = lane >> 2, tg = lane & 3;

    for (int g = 0; g < RR; g++) {
        // ---- stage B image for relation g (16KB) ----
        if (g > 0) __syncthreads();     // prior mainloop LDSMs done
        {
            const uint4* src = (const uint4*)(Bimg + (size_t)g * 16384);
            uint4* dst = (uint4*)(smem + OFF_B);
#pragma unroll
            for (int i = 0; i < 4; i++) dst[tid + i * 256] = src[tid + i * 256];
        }
        __syncthreads();

        float acc[2][4][4];
#pragma unroll
        for (int i = 0; i < 2; i++)
#pragma unroll
            for (int j = 0; j < 4; j++)
#pragma unroll
                for (int q = 0; q < 4; q++) acc[i][j][q] = 0.f;

#pragma unroll
        for (int ks = 0; ks < 8; ks++) {
            const int c = ks * 2;
            uint32_t afr[2][4], bfr[2][4];
#pragma unroll
            for (int mt = 0; mt < 2; mt++) {
                int m = a_m + mt * 16, cc = c + a_cb;
                uint32_t ad = abase + (uint32_t)m * 256 + ((cc ^ (m & 7)) << 4);
                ldsm4(ad, afr[mt][0], afr[mt][1], afr[mt][2], afr[mt][3]);
            }
#pragma unroll
            for (int pr = 0; pr < 2; pr++) {
                int n = b_n + pr * 16, cc = c + b_cb;
                uint32_t bd = bbase + (uint32_t)n * 256 + ((cc ^ (n & 7)) << 4);
                ldsm4(bd, bfr[pr][0], bfr[pr][1], bfr[pr][2], bfr[pr][3]);
            }
#pragma unroll
            for (int mt = 0; mt < 2; mt++)
#pragma unroll
                for (int nt = 0; nt < 4; nt++)
                    mma_f16(acc[mt][nt], afr[mt],
                            bfr[nt >> 1][(nt & 1) * 2],
                            bfr[nt >> 1][(nt & 1) * 2 + 1]);
        }

        // ---- epilogue: fp16 half2 stores ----
#pragma unroll
        for (int mt = 0; mt < 2; mt++)
#pragma unroll
            for (int nt = 0; nt < 4; nt++) {
                int row0 = m0 + mbase + mt * 16 + grp4;
                int col  = nbase + nt * 8 + tg * 2;
                if (row0 < M)
                    *(__half2*)&C[((size_t)g * M + row0) * OO + col] =
                        __floats2half2_rn(acc[mt][nt][0], acc[mt][nt][1]);
                int row1 = row0 + 8;
                if (row1 < M)
                    *(__half2*)&C[((size_t)g * M + row1) * OO + col] =
                        __floats2half2_rn(acc[mt][nt][2], acc[mt][nt][3]);
            }
    }
}

// ---------------------------------------------------------------------------
// SpMM: 8 lanes/edge, 2 edges/group; fp16 gathers (uint4/lane = 16B),
// products in fp32 rounded once to half2, fp16 v4.f16x2 red (16B covers
// 8 halves -> 8 red-lanes per edge instead of 16).
// block = 256 threads = 32 groups = 64 edges. grid = (10000, RR).
// ---------------------------------------------------------------------------
__global__ void __launch_bounds__(256)
spmm_kernel(const int* __restrict__ rows, const int* __restrict__ cols,
            const float* __restrict__ vals, const __half* __restrict__ tmp,
            __half* __restrict__ zh)
{
    const int rel = blockIdx.y;
    const int grp = threadIdx.x >> 3;
    const int l8  = threadIdx.x & 7;
    const int e   = blockIdx.x * 64 + grp * 2;
    const size_t eo = (size_t)rel * EE + e;

    int2 rw = make_int2(0, 0), cl = make_int2(0, 0);
    float2 vv = make_float2(0.f, 0.f);
    if (l8 == 0) {
        rw = *(const int2*)(rows + eo);
        cl = *(const int2*)(cols + eo);
        vv = *(const float2*)(vals + eo);
    }
    int   row0 = __shfl_sync(0xffffffffu, rw.x, 0, 8);
    int   row1 = __shfl_sync(0xffffffffu, rw.y, 0, 8);
    int   col0 = __shfl_sync(0xffffffffu, cl.x, 0, 8);
    int   col1 = __shfl_sync(0xffffffffu, cl.y, 0, 8);
    float v0   = __shfl_sync(0xffffffffu, vv.x, 0, 8);
    float v1   = __shfl_sync(0xffffffffu, vv.y, 0, 8);

    const uint4* tb = (const uint4*)(tmp + (size_t)rel * 100000 * OO);
    uint4 t0 = __ldg(tb + (size_t)col0 * 8 + l8);
    uint4 t1 = __ldg(tb + (size_t)col1 * 8 + l8);

    uint32_t p0[4], p1[4];
#pragma unroll
    for (int i = 0; i < 4; i++) {
        float2 f0 = __half22float2(*(__half2*)(&t0.x + i));
        float2 f1 = __half22float2(*(__half2*)(&t1.x + i));
        __half2 h0 = __floats2half2_rn(f0.x * v0, f0.y * v0);
        __half2 h1 = __floats2half2_rn(f1.x * v1, f1.y * v1);
        p0[i] = *(uint32_t*)&h0;
        p1[i] = *(uint32_t*)&h1;
    }

    __half* d0 = zh + (size_t)row0 * OO + l8 * 8;
    __half* d1 = zh + (size_t)row1 * OO + l8 * 8;
    asm volatile("red.global.add.noftz.v4.f16x2 [%0], {%1, %2, %3, %4};"
                 :: "l"(d0), "r"(p0[0]), "r"(p0[1]), "r"(p0[2]), "r"(p0[3])
                 : "memory");
    asm volatile("red.global.add.noftz.v4.f16x2 [%0], {%1, %2, %3, %4};"
                 :: "l"(d1), "r"(p1[0]), "r"(p1[1]), "r"(p1[2]), "r"(p1[3])
                 : "memory");
}

// ---------------------------------------------------------------------------
// zero (fp16 accumulators) / cvt_relu (fp16 -> fp32 out with ReLU)
// ---------------------------------------------------------------------------
__global__ void zero_kernel(float4* __restrict__ p, int n4)
{
    int i = blockIdx.x * blockDim.x + threadIdx.x;
    if (i < n4) p[i] = make_float4(0.f, 0.f, 0.f, 0.f);
}
__global__ void cvt_relu_kernel(const uint2* __restrict__ zh,
                                float4* __restrict__ out, int n)
{
    int i = blockIdx.x * blockDim.x + threadIdx.x;
    if (i >= n) return;
    uint2 h = __ldg(zh + i);
    float2 f0 = __half22float2(*(__half2*)&h.x);
    float2 f1 = __half22float2(*(__half2*)&h.y);
    out[i] = make_float4(fmaxf(f0.x, 0.f), fmaxf(f0.y, 0.f),
                         fmaxf(f1.x, 0.f), fmaxf(f1.y, 0.f));
}

// ---------------------------------------------------------------------------
// kernel_launch — R11 schedule with fp16 z accumulators:
//   cumsum -> [gemmV || zero(zh)] -> [spmmV || gemmU]
//   -> [spmmU || cvt_relu z_u] -> cvt_relu z_v ; join.
// ---------------------------------------------------------------------------
extern "C" void kernel_launch(void* const* d_in, const int* in_sizes, int n_in,
                              void* d_out, int out_size)
{
    const float* x_u  = (const float*)d_in[0];
    const float* x_v  = (const float*)d_in[1];
    const int*   srow = (const int*)d_in[2];
    const int*   scol = (const int*)d_in[3];
    const float* sval = (const float*)d_in[4];
    const float* wu   = (const float*)d_in[5];
    const float* wv   = (const float*)d_in[6];

    float* out = (float*)d_out;

    __half *tmpU, *tmpV, *zh;
    unsigned char *BiU, *BiV;
    cudaGetSymbolAddress((void**)&tmpU, g_tmpU);
    cudaGetSymbolAddress((void**)&tmpV, g_tmpV);
    cudaGetSymbolAddress((void**)&zh, g_zh);
    cudaGetSymbolAddress((void**)&BiU, g_BimgU);
    cudaGetSymbolAddress((void**)&BiV, g_BimgV);

    __half* zh_u = zh;
    __half* zh_v = zh + (size_t)NU * OO;
    float*  out_v = out + (size_t)NU * OO;

    static cudaStream_t s2 = nullptr;
    static cudaEvent_t evFork, evZero, evGemmU, evZu, evJoin;
    if (!s2) {
        cudaStreamCreateWithFlags(&s2, cudaStreamNonBlocking);
        cudaEventCreateWithFlags(&evFork,  cudaEventDisableTiming);
        cudaEventCreateWithFlags(&evZero,  cudaEventDisableTiming);
        cudaEventCreateWithFlags(&evGemmU, cudaEventDisableTiming);
        cudaEventCreateWithFlags(&evZu,    cudaEventDisableTiming);
        cudaEventCreateWithFlags(&evJoin,  cudaEventDisableTiming);
        cudaFuncSetAttribute(gemm_tc_kernel,
                             cudaFuncAttributeMaxDynamicSharedMemorySize,
                             GT_SMEM);
    }

    const int nh4 = (int)((size_t)2 * 100000 * OO / 8);   // zh as float4: 1.6M
    const int nc  = (int)((size_t)NU * OO / 4);           // per-side cvt: 1.6M

    // stage 0: cumsum (stream 0), then fork
    cumsum_pack_kernel<<<dim3((DD * OO + 255) / 256, 2), 256>>>(wu, wv, BiU, BiV);
    cudaEventRecord(evFork, 0);
    cudaStreamWaitEvent(s2, evFork, 0);

    // stage 1: gemmV (stream 0)  ||  zero zh (s2)
    zero_kernel<<<(nh4 + 255) / 256, 256, 0, s2>>>((float4*)zh, nh4);
    gemm_tc_kernel<<<GEMM_TILES, 256, GT_SMEM>>>(x_v, BiV, tmpV, NVV);
    cudaEventRecord(evZero, s2);
    cudaStreamWaitEvent(0, evZero, 0);       // spmmV needs zh zeroed
    cudaEventRecord(evFork, 0);              // gemmV + zero both done here
    cudaStreamWaitEvent(s2, evFork, 0);

    // stage 2: spmmV -> zh_u (stream 0)  ||  gemmU -> tmpU (s2)
    gemm_tc_kernel<<<GEMM_TILES, 256, GT_SMEM, s2>>>(x_u, BiU, tmpU, NU);
    spmm_kernel<<<dim3(SPMM_BPR, RR), 256>>>(srow, scol, sval, tmpV, zh_u);
    cudaEventRecord(evGemmU, s2);
    cudaStreamWaitEvent(0, evGemmU, 0);      // spmmU needs tmpU
    cudaEventRecord(evZu, 0);                // zh_u final after spmmV
    cudaStreamWaitEvent(s2, evZu, 0);

    // stage 3: spmmU -> zh_v (stream 0)  ||  cvt_relu z_u (s2)
    cvt_relu_kernel<<<(nc + 255) / 256, 256, 0, s2>>>((const uint2*)zh_u,
                                                      (float4*)out, nc);
    spmm_kernel<<<dim3(SPMM_BPR, RR), 256>>>(scol, srow, sval, tmpU, zh_v);

    // stage 4: cvt_relu z_v (stream 0); join s2
    cvt_relu_kernel<<<(nc + 255) / 256, 256>>>((const uint2*)zh_v,
                                               (float4*)out_v, nc);
    cudaEventRecord(evJoin, s2);
    cudaStreamWaitEvent(0, evJoin, 0);
}